// round 3
// baseline (speedup 1.0000x reference)
#include <cuda_runtime.h>
#include <cuda_bf16.h>
#include <cstdint>
#include <cstddef>

// ----------------------------------------------------------------------------
// CRFModel: 2-layer BiLSTM (H=200) + Linear(K=9) + CRF NLL
// B=64, T=512, E=1024. Output: scalar f32 loss.
// ----------------------------------------------------------------------------

#define BB   64
#define TT   512
#define EE   1024
#define HH   200
#define NG   1600   // 2 dirs x 4 gates x H
#define KTAG 9

// ---------------- scratch (device globals; no cudaMalloc allowed) ------------
__device__ float g_xp[BB * TT * NG];          // gate pre-activations (reused per layer)
__device__ float g_h0[BB * TT * 2 * HH];      // layer0 output (concat f/b)
__device__ float g_h1[BB * TT * 2 * HH];      // layer1 output
__device__ float g_wpack[NG * EE];            // packed input-proj weights
__device__ float g_bpack[NG];                 // packed (b_ih + b_hh)
__device__ float g_em[BB * TT * KTAG];        // emissions
__device__ float g_hx[2 * 8 * 2 * 8 * HH];    // h exchange: (dir,bg) x parity x b x j
__device__ int   g_cnt[2][2][8][TT];          // layer,dir,bg,step counters
__device__ float g_nll[BB];

// ---------------- init: zero sync counters -----------------------------------
__global__ void init_kernel() {
    int idx = blockIdx.x * blockDim.x + threadIdx.x;
    int* c = &g_cnt[0][0][0][0];
    if (idx < 2 * 2 * 8 * TT) c[idx] = 0;
}

// ---------------- pack concat(w_f, w_b) + combined bias ----------------------
__global__ void pack_kernel(const float* __restrict__ wf, const float* __restrict__ wb,
                            const float* __restrict__ bif, const float* __restrict__ bhf,
                            const float* __restrict__ bib, const float* __restrict__ bhb,
                            int K) {
    int idx = blockIdx.x * blockDim.x + threadIdx.x;
    int total = NG * K;
    for (int i = idx; i < total; i += gridDim.x * blockDim.x) {
        int row = i / K, col = i - row * K;
        g_wpack[i] = (row < 800) ? wf[row * K + col] : wb[(row - 800) * K + col];
    }
    if (idx < NG)
        g_bpack[idx] = (idx < 800) ? (bif[idx] + bhf[idx])
                                   : (bib[idx - 800] + bhb[idx - 800]);
}

// ---------------- SGEMM: g_xp[M,1600] = A[M,K] @ g_wpack[1600,K]^T + g_bpack --
// BM=128, BN=64, BK=16, 256 threads, 8x4 microtiles. layer selects A source.
__global__ void __launch_bounds__(256) gemm_kernel(const float* __restrict__ Aext,
                                                   int K, int layer) {
    __shared__ __align__(16) float As[16][132];
    __shared__ __align__(16) float Bs[16][68];
    const float* __restrict__ A = layer ? g_h0 : Aext;
    const float* __restrict__ W = g_wpack;
    const int bx = blockIdx.x;     // N tile (64 wide), N = 1600
    const int by = blockIdx.y;     // M tile (128 tall)
    const int tid = threadIdx.x;
    const int ty = tid >> 4, tx = tid & 15;
    const float* Ab = A + (size_t)by * 128 * K;
    const float* Wb = W + (size_t)bx * 64 * K;
    const int lr = tid >> 2;           // 0..63
    const int lc = (tid & 3) << 2;     // 0,4,8,12

    float acc[8][4];
#pragma unroll
    for (int i = 0; i < 8; ++i)
#pragma unroll
        for (int j = 0; j < 4; ++j) acc[i][j] = 0.f;

    for (int k0 = 0; k0 < K; k0 += 16) {
        float4 a0 = *(const float4*)(Ab + (size_t)lr * K + k0 + lc);
        float4 a1 = *(const float4*)(Ab + (size_t)(lr + 64) * K + k0 + lc);
        float4 w0 = *(const float4*)(Wb + (size_t)lr * K + k0 + lc);
        As[lc + 0][lr] = a0.x; As[lc + 1][lr] = a0.y; As[lc + 2][lr] = a0.z; As[lc + 3][lr] = a0.w;
        As[lc + 0][lr + 64] = a1.x; As[lc + 1][lr + 64] = a1.y; As[lc + 2][lr + 64] = a1.z; As[lc + 3][lr + 64] = a1.w;
        Bs[lc + 0][lr] = w0.x; Bs[lc + 1][lr] = w0.y; Bs[lc + 2][lr] = w0.z; Bs[lc + 3][lr] = w0.w;
        __syncthreads();
#pragma unroll
        for (int k = 0; k < 16; ++k) {
            float4 ar0 = *(const float4*)&As[k][ty * 8];
            float4 ar1 = *(const float4*)&As[k][ty * 8 + 4];
            float4 br  = *(const float4*)&Bs[k][tx * 4];
            float av[8] = {ar0.x, ar0.y, ar0.z, ar0.w, ar1.x, ar1.y, ar1.z, ar1.w};
            float bv[4] = {br.x, br.y, br.z, br.w};
#pragma unroll
            for (int i = 0; i < 8; ++i)
#pragma unroll
                for (int j = 0; j < 4; ++j) acc[i][j] += av[i] * bv[j];
        }
        __syncthreads();
    }
    float4 bvv = *(const float4*)(g_bpack + bx * 64 + tx * 4);
#pragma unroll
    for (int i = 0; i < 8; ++i) {
        size_t row = (size_t)by * 128 + ty * 8 + i;
        float4 o;
        o.x = acc[i][0] + bvv.x; o.y = acc[i][1] + bvv.y;
        o.z = acc[i][2] + bvv.z; o.w = acc[i][3] + bvv.w;
        *(float4*)(g_xp + row * NG + bx * 64 + tx * 4) = o;
    }
}

// ---------------- BiLSTM recurrence ------------------------------------------
// 128 blocks = dir(2) x batch-group(8) x h-slice(8). Weight-stationary in regs.
__device__ __forceinline__ float sigm(float x) { return 1.f / (1.f + __expf(-x)); }

__global__ void __launch_bounds__(256, 1) lstm_kernel(
    const float* __restrict__ whh_f,   // 800x200
    const float* __restrict__ whh_b,   // 800x200
    int layer) {
    const int blk = blockIdx.x;
    const int dir = blk >> 6;
    const int bg  = (blk >> 3) & 7;
    const int hsl = blk & 7;
    const int j0  = hsl * 25;
    const int b0  = bg * 8;
    const float* __restrict__ whh = dir ? whh_b : whh_f;
    float* __restrict__ hout = layer ? g_h1 : g_h0;
    const float* __restrict__ xp = g_xp;
    const int tid = threadIdx.x;

    __shared__ __align__(16) float h_s[1600];   // 8 batch x 200 h
    __shared__ float part[8000];                // 8 x 100 rows x 10 partials

    const int rg = tid / 10;        // row group (4 rows), valid tid<250
    const int kc = tid % 10;        // k chunk (20 k)
    const bool is_comp = (tid < 250);
    const int rb = tid / 25;        // reduce: batch in group, valid tid<200
    const int rj = tid % 25;        // reduce: h index in slice
    const bool is_red = (tid < 200);

    // weight registers: 4 rows x 20 k per compute thread
    float w[4][20];
    if (is_comp) {
#pragma unroll
        for (int i = 0; i < 4; ++i) {
            int r = rg * 4 + i;                       // local row 0..99
            int g = (r / 25) * 200 + j0 + (r % 25);   // gate row in w_hh
            const float* wr = whh + g * 200 + kc * 20;
#pragma unroll
            for (int k = 0; k < 20; ++k) w[i][k] = wr[k];
        }
    }
    for (int i = tid; i < 1600; i += 256) h_s[i] = 0.f;
    float creg = 0.f;

    int* cnt = &g_cnt[layer][dir][bg][0];
    float* hx = g_hx + (size_t)(dir * 8 + bg) * 3200;  // 2 parities x 1600

    __syncthreads();

    const int xoff = dir * 800 + j0;
    for (int t = 0; t < TT; ++t) {
        const int tt = dir ? (TT - 1 - t) : t;
        // prefetch this step's xp gates
        float xr0 = 0.f, xr1 = 0.f, xr2 = 0.f, xr3 = 0.f;
        if (is_red) {
            const float* xpp = xp + ((size_t)(b0 + rb) * TT + tt) * NG + xoff + rj;
            xr0 = xpp[0]; xr1 = xpp[200]; xr2 = xpp[400]; xr3 = xpp[600];
        }
        // partial dot products: h(t-1) @ w_hh^T
        if (is_comp) {
#pragma unroll 1
            for (int b = 0; b < 8; ++b) {
                const float4* hv4 = ((const float4*)h_s) + b * 50 + kc * 5;
                float a0 = 0.f, a1 = 0.f, a2 = 0.f, a3 = 0.f;
#pragma unroll
                for (int kk = 0; kk < 5; ++kk) {
                    float4 hv = hv4[kk];
                    const int kb = kk * 4;
                    a0 += w[0][kb] * hv.x + w[0][kb + 1] * hv.y + w[0][kb + 2] * hv.z + w[0][kb + 3] * hv.w;
                    a1 += w[1][kb] * hv.x + w[1][kb + 1] * hv.y + w[1][kb + 2] * hv.z + w[1][kb + 3] * hv.w;
                    a2 += w[2][kb] * hv.x + w[2][kb + 1] * hv.y + w[2][kb + 2] * hv.z + w[2][kb + 3] * hv.w;
                    a3 += w[3][kb] * hv.x + w[3][kb + 1] * hv.y + w[3][kb + 2] * hv.z + w[3][kb + 3] * hv.w;
                }
                int pb = (b * 100 + rg * 4) * 10 + kc;
                part[pb]      = a0;
                part[pb + 10] = a1;
                part[pb + 20] = a2;
                part[pb + 30] = a3;
            }
        }
        __syncthreads();
        // reduce + gate activations
        if (is_red) {
            const float* p = part + (rb * 100 + rj) * 10;
            float si = xr0, sf = xr1, sg = xr2, so = xr3;
#pragma unroll
            for (int k = 0; k < 10; ++k) {
                si += p[k]; sf += p[250 + k]; sg += p[500 + k]; so += p[750 + k];
            }
            creg = sigm(sf) * creg + sigm(si) * tanhf(sg);
            float hval = sigm(so) * tanhf(creg);
            hx[(t & 1) * 1600 + rb * 200 + j0 + rj] = hval;
            hout[((size_t)(b0 + rb) * TT + tt) * 400 + dir * 200 + j0 + rj] = hval;
            __threadfence();
        }
        if (t == TT - 1) break;
        __syncthreads();
        if (tid == 0) {
            atomicAdd(&cnt[t], 1);
            while (((volatile int*)cnt)[t] != 8) { }
            __threadfence();
        }
        __syncthreads();
        const float* src = hx + (t & 1) * 1600;
        for (int i = tid; i < 1600; i += 256) h_s[i] = src[i];
        __syncthreads();
    }
}

// ---------------- emissions: relu(h1) @ w_out^T + b_out ----------------------
__global__ void __launch_bounds__(256) emis_kernel(const float* __restrict__ wout,
                                                   const float* __restrict__ bout) {
    __shared__ float ws[KTAG * 400];
    __shared__ float bs[KTAG];
    const int tid = threadIdx.x;
    for (int i = tid; i < KTAG * 400; i += 256) ws[i] = wout[i];
    if (tid < KTAG) bs[tid] = bout[tid];
    __syncthreads();
    const int warp = tid >> 5, lane = tid & 31;
    const size_t row = (size_t)blockIdx.x * 8 + warp;   // < 32768
    const float* hr = g_h1 + row * 400;
    float acc[KTAG];
#pragma unroll
    for (int k = 0; k < KTAG; ++k) acc[k] = 0.f;
    for (int d = lane * 4; d < 400; d += 128) {
        float4 hv = *(const float4*)(hr + d);
        hv.x = fmaxf(hv.x, 0.f); hv.y = fmaxf(hv.y, 0.f);
        hv.z = fmaxf(hv.z, 0.f); hv.w = fmaxf(hv.w, 0.f);
#pragma unroll
        for (int k = 0; k < KTAG; ++k) {
            const float* wk = ws + k * 400 + d;
            acc[k] += hv.x * wk[0] + hv.y * wk[1] + hv.z * wk[2] + hv.w * wk[3];
        }
    }
#pragma unroll
    for (int k = 0; k < KTAG; ++k)
#pragma unroll
        for (int off = 16; off > 0; off >>= 1)
            acc[k] += __shfl_xor_sync(0xffffffffu, acc[k], off);
    if (lane == 0) {
#pragma unroll
        for (int k = 0; k < KTAG; ++k) g_em[row * KTAG + k] = acc[k] + bs[k];
    }
}

// ---------------- CRF NLL: one warp per batch ---------------------------------
// NOTE: mask is int32 on device (bool -> int32), NOT bytes.
__global__ void crf_kernel(const int* __restrict__ mask,
                           const int* __restrict__ y,
                           const float* __restrict__ start,
                           const float* __restrict__ endv,
                           const float* __restrict__ trans) {
    const int b = blockIdx.x;
    const int lane = threadIdx.x;
    const float* emb = g_em + (size_t)b * TT * KTAG;
    const int* yb = y + b * TT;
    const int* mb = mask + b * TT;

    float tr[KTAG];
#pragma unroll
    for (int i = 0; i < KTAG; ++i)
        tr[i] = (lane < KTAG) ? trans[i * KTAG + lane] : 0.f;
    float alpha = (lane < KTAG) ? (start[lane] + emb[lane]) : -1e30f;

    // numerator pieces (lane-parallel over t)
    float num = 0.f; int msum = 0;
    for (int t = lane; t < TT; t += 32) {
        int mt = mb[t] ? 1 : 0;
        msum += mt;
        if (t >= 1 && mt) {
            int yt = yb[t], yp = yb[t - 1];
            num += emb[t * KTAG + yt] + trans[yp * KTAG + yt];
        }
    }
#pragma unroll
    for (int off = 16; off > 0; off >>= 1) {
        num  += __shfl_xor_sync(0xffffffffu, num, off);
        msum += __shfl_xor_sync(0xffffffffu, msum, off);
    }

    // forward recurrence (K=9 in lanes 0..8)
    for (int t = 1; t < TT; ++t) {
        float em_t = (lane < KTAG) ? emb[t * KTAG + lane] : 0.f;
        float v[KTAG], m = -1e30f;
#pragma unroll
        for (int i = 0; i < KTAG; ++i) {
            v[i] = __shfl_sync(0xffffffffu, alpha, i) + tr[i];
            m = fmaxf(m, v[i]);
        }
        float s = 0.f;
#pragma unroll
        for (int i = 0; i < KTAG; ++i) s += __expf(v[i] - m);
        float nxt = m + __logf(s) + em_t;
        alpha = mb[t] ? nxt : alpha;
    }

    // denominator = logsumexp(alpha + end)
    float av = (lane < KTAG) ? (alpha + endv[lane]) : -1e30f;
    float m = av;
#pragma unroll
    for (int off = 16; off > 0; off >>= 1)
        m = fmaxf(m, __shfl_xor_sync(0xffffffffu, m, off));
    float s = __expf(av - m);
#pragma unroll
    for (int off = 16; off > 0; off >>= 1)
        s += __shfl_xor_sync(0xffffffffu, s, off);
    float den = m + __logf(s);

    if (lane == 0) {
        int last = msum - 1;
        float numerator = num + start[yb[0]] + emb[yb[0]] + endv[yb[last]];
        g_nll[b] = den - numerator;
    }
}

// ---------------- final deterministic sum -------------------------------------
__global__ void final_kernel(float* __restrict__ out) {
    if (threadIdx.x == 0 && blockIdx.x == 0) {
        float s = 0.f;
        for (int b = 0; b < BB; ++b) s += g_nll[b];
        out[0] = s;
    }
}

// ---------------- launch -------------------------------------------------------
extern "C" void kernel_launch(void* const* d_in, const int* in_sizes, int n_in,
                              void* d_out, int out_size) {
    const float* emb   = (const float*)d_in[0];
    const int*   mask  = (const int*)d_in[1];     // bool stored as int32
    const int*   y     = (const int*)d_in[2];
    const float* w_ih0f = (const float*)d_in[3];
    const float* w_hh0f = (const float*)d_in[4];
    const float* b_ih0f = (const float*)d_in[5];
    const float* b_hh0f = (const float*)d_in[6];
    const float* w_ih0b = (const float*)d_in[7];
    const float* w_hh0b = (const float*)d_in[8];
    const float* b_ih0b = (const float*)d_in[9];
    const float* b_hh0b = (const float*)d_in[10];
    const float* w_ih1f = (const float*)d_in[11];
    const float* w_hh1f = (const float*)d_in[12];
    const float* b_ih1f = (const float*)d_in[13];
    const float* b_hh1f = (const float*)d_in[14];
    const float* w_ih1b = (const float*)d_in[15];
    const float* w_hh1b = (const float*)d_in[16];
    const float* b_ih1b = (const float*)d_in[17];
    const float* b_hh1b = (const float*)d_in[18];
    const float* w_out  = (const float*)d_in[19];
    const float* b_out  = (const float*)d_in[20];
    const float* crf_s  = (const float*)d_in[21];
    const float* crf_e  = (const float*)d_in[22];
    const float* crf_t  = (const float*)d_in[23];
    float* out = (float*)d_out;

    init_kernel<<<64, 256>>>();

    // ---- layer 0 ----
    pack_kernel<<<2048, 256>>>(w_ih0f, w_ih0b, b_ih0f, b_hh0f, b_ih0b, b_hh0b, EE);
    {
        dim3 grid(NG / 64, (BB * TT) / 128);
        gemm_kernel<<<grid, 256>>>(emb, EE, 0);
    }
    lstm_kernel<<<128, 256>>>(w_hh0f, w_hh0b, 0);

    // ---- layer 1 ----
    pack_kernel<<<2048, 256>>>(w_ih1f, w_ih1b, b_ih1f, b_hh1f, b_ih1b, b_hh1b, 2 * HH);
    {
        dim3 grid(NG / 64, (BB * TT) / 128);
        gemm_kernel<<<grid, 256>>>(nullptr, 2 * HH, 1);
    }
    lstm_kernel<<<128, 256>>>(w_hh1f, w_hh1b, 1);

    // ---- emissions + CRF ----
    emis_kernel<<<(BB * TT) / 8, 256>>>(w_out, b_out);
    crf_kernel<<<BB, 32>>>(mask, y, crf_s, crf_e, crf_t);
    final_kernel<<<1, 32>>>(out);
}

// round 4
// speedup vs baseline: 1.1686x; 1.1686x over previous
#include <cuda_runtime.h>
#include <cuda_bf16.h>
#include <cstdint>
#include <cstddef>

// ----------------------------------------------------------------------------
// CRFModel: 2-layer BiLSTM (H=200) + Linear(K=9) + CRF NLL
// B=64, T=512, E=1024. Output: scalar f32 loss.
// Round 3: input-projection GEMMs moved to tensor cores (mma.sync tf32).
// ----------------------------------------------------------------------------

#define BB   64
#define TT   512
#define EE   1024
#define HH   200
#define NG   1600   // 2 dirs x 4 gates x H
#define KTAG 9

// ---------------- scratch (device globals; no cudaMalloc allowed) ------------
__device__ float g_xp[BB * TT * NG];          // gate pre-activations (reused per layer)
__device__ float g_h0[BB * TT * 2 * HH];      // layer0 output (concat f/b)
__device__ float g_h1[BB * TT * 2 * HH];      // layer1 output
__device__ float g_wpack[NG * EE];            // packed input-proj weights
__device__ float g_bpack[NG];                 // packed (b_ih + b_hh)
__device__ float g_em[BB * TT * KTAG];        // emissions
__device__ float g_hx[2 * 8 * 2 * 8 * HH];    // h exchange: (dir,bg) x parity x b x j
__device__ int   g_cnt[2][2][8][TT];          // layer,dir,bg,step counters
__device__ float g_nll[BB];

// ---------------- init: zero sync counters -----------------------------------
__global__ void init_kernel() {
    int idx = blockIdx.x * blockDim.x + threadIdx.x;
    int* c = &g_cnt[0][0][0][0];
    if (idx < 2 * 2 * 8 * TT) c[idx] = 0;
}

// ---------------- pack concat(w_f, w_b) + combined bias ----------------------
__global__ void pack_kernel(const float* __restrict__ wf, const float* __restrict__ wb,
                            const float* __restrict__ bif, const float* __restrict__ bhf,
                            const float* __restrict__ bib, const float* __restrict__ bhb,
                            int K) {
    int idx = blockIdx.x * blockDim.x + threadIdx.x;
    int total = NG * K;
    for (int i = idx; i < total; i += gridDim.x * blockDim.x) {
        int row = i / K, col = i - row * K;
        g_wpack[i] = (row < 800) ? wf[row * K + col] : wb[(row - 800) * K + col];
    }
    if (idx < NG)
        g_bpack[idx] = (idx < 800) ? (bif[idx] + bhf[idx])
                                   : (bib[idx - 800] + bhb[idx - 800]);
}

// ---------------- tensor-core GEMM (tf32 mma.sync) ---------------------------
// g_xp[M,1600] = A[M,K] @ g_wpack[1600,K]^T + g_bpack
// BM=128, BN=64, BK=8, 256 threads = 8 warps (4 m x 2 n), warp tile 32x32.
__device__ __forceinline__ float tf32r(float x) {
    unsigned u;
    asm("cvt.rna.tf32.f32 %0, %1;" : "=r"(u) : "f"(x));
    return __uint_as_float(u);
}
__device__ __forceinline__ void mma_tf32(float* c, const unsigned* a, const unsigned* b) {
    asm volatile(
        "mma.sync.aligned.m16n8k8.row.col.f32.tf32.tf32.f32 "
        "{%0,%1,%2,%3}, {%4,%5,%6,%7}, {%8,%9}, {%0,%1,%2,%3};\n"
        : "+f"(c[0]), "+f"(c[1]), "+f"(c[2]), "+f"(c[3])
        : "r"(a[0]), "r"(a[1]), "r"(a[2]), "r"(a[3]), "r"(b[0]), "r"(b[1]));
}

__global__ void __launch_bounds__(256) gemm_tf32_kernel(const float* __restrict__ Aext,
                                                        int K, int layer) {
    __shared__ float As[2][8][136];   // [k][m], padded: bank = (8k + m) % 32
    __shared__ float Bs[2][8][72];    // [k][n], padded: bank = (8k + n) % 32
    const float* __restrict__ A = layer ? g_h0 : Aext;
    const int bx = blockIdx.x;        // N tile (64)
    const int by = blockIdx.y;        // M tile (128)
    const int tid = threadIdx.x;
    const int wid = tid >> 5, lane = tid & 31;
    const int wm = (wid & 3) * 32;    // warp m offset
    const int wn = (wid >> 2) * 32;   // warp n offset
    const float* Ab = A + (size_t)by * 128 * K;
    const float* Wb = g_wpack + (size_t)bx * 64 * K;

    // global loader mapping
    const int am = tid >> 1;          // 0..127 (A row)
    const int ak = (tid & 1) * 4;     // 0 or 4 (A k sub)
    const int bn = tid >> 2;          // 0..63  (B row = n)
    const int bk = (tid & 3) * 2;     // 0,2,4,6 (B k sub)

    float c[2][4][4];
#pragma unroll
    for (int mi = 0; mi < 2; ++mi)
#pragma unroll
        for (int ni = 0; ni < 4; ++ni)
#pragma unroll
            for (int q = 0; q < 4; ++q) c[mi][ni][q] = 0.f;

    const int row = lane >> 2;        // 0..7
    const int kq  = lane & 3;         // 0..3

    // prefetch stage 0
    float4 areg = *(const float4*)(Ab + (size_t)am * K + ak);
    float2 breg = *(const float2*)(Wb + (size_t)bn * K + bk);

    int buf = 0;
    for (int k0 = 0; k0 < K; k0 += 8) {
        // commit prefetched regs to smem (tf32-rounded)
        As[buf][ak + 0][am] = tf32r(areg.x);
        As[buf][ak + 1][am] = tf32r(areg.y);
        As[buf][ak + 2][am] = tf32r(areg.z);
        As[buf][ak + 3][am] = tf32r(areg.w);
        Bs[buf][bk + 0][bn] = tf32r(breg.x);
        Bs[buf][bk + 1][bn] = tf32r(breg.y);
        __syncthreads();

        // prefetch next stage
        if (k0 + 8 < K) {
            areg = *(const float4*)(Ab + (size_t)am * K + k0 + 8 + ak);
            breg = *(const float2*)(Wb + (size_t)bn * K + k0 + 8 + bk);
        }

        // fragments
        unsigned a[2][4], b[4][2];
#pragma unroll
        for (int mi = 0; mi < 2; ++mi) {
            a[mi][0] = __float_as_uint(As[buf][kq    ][wm + mi * 16 + row    ]);
            a[mi][1] = __float_as_uint(As[buf][kq    ][wm + mi * 16 + row + 8]);
            a[mi][2] = __float_as_uint(As[buf][kq + 4][wm + mi * 16 + row    ]);
            a[mi][3] = __float_as_uint(As[buf][kq + 4][wm + mi * 16 + row + 8]);
        }
#pragma unroll
        for (int ni = 0; ni < 4; ++ni) {
            b[ni][0] = __float_as_uint(Bs[buf][kq    ][wn + ni * 8 + row]);
            b[ni][1] = __float_as_uint(Bs[buf][kq + 4][wn + ni * 8 + row]);
        }
#pragma unroll
        for (int mi = 0; mi < 2; ++mi)
#pragma unroll
            for (int ni = 0; ni < 4; ++ni)
                mma_tf32(c[mi][ni], a[mi], b[ni]);

        buf ^= 1;
    }

    // epilogue: bias + store (c0,c1 -> row, cols colq..colq+1; c2,c3 -> row+8)
    const int colq = (lane & 3) * 2;
#pragma unroll
    for (int ni = 0; ni < 4; ++ni) {
        const int cc = bx * 64 + wn + ni * 8 + colq;
        const float b0 = g_bpack[cc], b1 = g_bpack[cc + 1];
#pragma unroll
        for (int mi = 0; mi < 2; ++mi) {
            const size_t r0 = (size_t)by * 128 + wm + mi * 16 + row;
            float2 o0, o1;
            o0.x = c[mi][ni][0] + b0; o0.y = c[mi][ni][1] + b1;
            o1.x = c[mi][ni][2] + b0; o1.y = c[mi][ni][3] + b1;
            *(float2*)(g_xp + r0 * NG + cc)       = o0;
            *(float2*)(g_xp + (r0 + 8) * NG + cc) = o1;
        }
    }
}

// ---------------- BiLSTM recurrence ------------------------------------------
// 128 blocks = dir(2) x batch-group(8) x h-slice(8). Weight-stationary in regs.
__device__ __forceinline__ float sigm(float x) { return 1.f / (1.f + __expf(-x)); }

__global__ void __launch_bounds__(256, 1) lstm_kernel(
    const float* __restrict__ whh_f,   // 800x200
    const float* __restrict__ whh_b,   // 800x200
    int layer) {
    const int blk = blockIdx.x;
    const int dir = blk >> 6;
    const int bg  = (blk >> 3) & 7;
    const int hsl = blk & 7;
    const int j0  = hsl * 25;
    const int b0  = bg * 8;
    const float* __restrict__ whh = dir ? whh_b : whh_f;
    float* __restrict__ hout = layer ? g_h1 : g_h0;
    const float* __restrict__ xp = g_xp;
    const int tid = threadIdx.x;

    __shared__ __align__(16) float h_s[1600];   // 8 batch x 200 h
    __shared__ float part[8000];                // 8 x 100 rows x 10 partials

    const int rg = tid / 10;        // row group (4 rows), valid tid<250
    const int kc = tid % 10;        // k chunk (20 k)
    const bool is_comp = (tid < 250);
    const int rb = tid / 25;        // reduce: batch in group, valid tid<200
    const int rj = tid % 25;        // reduce: h index in slice
    const bool is_red = (tid < 200);

    // weight registers: 4 rows x 20 k per compute thread
    float w[4][20];
    if (is_comp) {
#pragma unroll
        for (int i = 0; i < 4; ++i) {
            int r = rg * 4 + i;                       // local row 0..99
            int g = (r / 25) * 200 + j0 + (r % 25);   // gate row in w_hh
            const float* wr = whh + g * 200 + kc * 20;
#pragma unroll
            for (int k = 0; k < 20; ++k) w[i][k] = wr[k];
        }
    }
    for (int i = tid; i < 1600; i += 256) h_s[i] = 0.f;
    float creg = 0.f;

    int* cnt = &g_cnt[layer][dir][bg][0];
    float* hx = g_hx + (size_t)(dir * 8 + bg) * 3200;  // 2 parities x 1600

    __syncthreads();

    const int xoff = dir * 800 + j0;
    for (int t = 0; t < TT; ++t) {
        const int tt = dir ? (TT - 1 - t) : t;
        // prefetch this step's xp gates
        float xr0 = 0.f, xr1 = 0.f, xr2 = 0.f, xr3 = 0.f;
        if (is_red) {
            const float* xpp = xp + ((size_t)(b0 + rb) * TT + tt) * NG + xoff + rj;
            xr0 = xpp[0]; xr1 = xpp[200]; xr2 = xpp[400]; xr3 = xpp[600];
        }
        // partial dot products: h(t-1) @ w_hh^T
        if (is_comp) {
#pragma unroll 1
            for (int b = 0; b < 8; ++b) {
                const float4* hv4 = ((const float4*)h_s) + b * 50 + kc * 5;
                float a0 = 0.f, a1 = 0.f, a2 = 0.f, a3 = 0.f;
#pragma unroll
                for (int kk = 0; kk < 5; ++kk) {
                    float4 hv = hv4[kk];
                    const int kb = kk * 4;
                    a0 += w[0][kb] * hv.x + w[0][kb + 1] * hv.y + w[0][kb + 2] * hv.z + w[0][kb + 3] * hv.w;
                    a1 += w[1][kb] * hv.x + w[1][kb + 1] * hv.y + w[1][kb + 2] * hv.z + w[1][kb + 3] * hv.w;
                    a2 += w[2][kb] * hv.x + w[2][kb + 1] * hv.y + w[2][kb + 2] * hv.z + w[2][kb + 3] * hv.w;
                    a3 += w[3][kb] * hv.x + w[3][kb + 1] * hv.y + w[3][kb + 2] * hv.z + w[3][kb + 3] * hv.w;
                }
                int pb = (b * 100 + rg * 4) * 10 + kc;
                part[pb]      = a0;
                part[pb + 10] = a1;
                part[pb + 20] = a2;
                part[pb + 30] = a3;
            }
        }
        __syncthreads();
        // reduce + gate activations
        if (is_red) {
            const float* p = part + (rb * 100 + rj) * 10;
            float si = xr0, sf = xr1, sg = xr2, so = xr3;
#pragma unroll
            for (int k = 0; k < 10; ++k) {
                si += p[k]; sf += p[250 + k]; sg += p[500 + k]; so += p[750 + k];
            }
            creg = sigm(sf) * creg + sigm(si) * tanhf(sg);
            float hval = sigm(so) * tanhf(creg);
            hx[(t & 1) * 1600 + rb * 200 + j0 + rj] = hval;
            hout[((size_t)(b0 + rb) * TT + tt) * 400 + dir * 200 + j0 + rj] = hval;
            __threadfence();
        }
        if (t == TT - 1) break;
        __syncthreads();
        if (tid == 0) {
            atomicAdd(&cnt[t], 1);
            while (((volatile int*)cnt)[t] != 8) { }
            __threadfence();
        }
        __syncthreads();
        const float* src = hx + (t & 1) * 1600;
        for (int i = tid; i < 1600; i += 256) h_s[i] = src[i];
        __syncthreads();
    }
}

// ---------------- emissions: relu(h1) @ w_out^T + b_out ----------------------
__global__ void __launch_bounds__(256) emis_kernel(const float* __restrict__ wout,
                                                   const float* __restrict__ bout) {
    __shared__ float ws[KTAG * 400];
    __shared__ float bs[KTAG];
    const int tid = threadIdx.x;
    for (int i = tid; i < KTAG * 400; i += 256) ws[i] = wout[i];
    if (tid < KTAG) bs[tid] = bout[tid];
    __syncthreads();
    const int warp = tid >> 5, lane = tid & 31;
    const size_t row = (size_t)blockIdx.x * 8 + warp;   // < 32768
    const float* hr = g_h1 + row * 400;
    float acc[KTAG];
#pragma unroll
    for (int k = 0; k < KTAG; ++k) acc[k] = 0.f;
    for (int d = lane * 4; d < 400; d += 128) {
        float4 hv = *(const float4*)(hr + d);
        hv.x = fmaxf(hv.x, 0.f); hv.y = fmaxf(hv.y, 0.f);
        hv.z = fmaxf(hv.z, 0.f); hv.w = fmaxf(hv.w, 0.f);
#pragma unroll
        for (int k = 0; k < KTAG; ++k) {
            const float* wk = ws + k * 400 + d;
            acc[k] += hv.x * wk[0] + hv.y * wk[1] + hv.z * wk[2] + hv.w * wk[3];
        }
    }
#pragma unroll
    for (int k = 0; k < KTAG; ++k)
#pragma unroll
        for (int off = 16; off > 0; off >>= 1)
            acc[k] += __shfl_xor_sync(0xffffffffu, acc[k], off);
    if (lane == 0) {
#pragma unroll
        for (int k = 0; k < KTAG; ++k) g_em[row * KTAG + k] = acc[k] + bs[k];
    }
}

// ---------------- CRF NLL: one warp per batch ---------------------------------
// NOTE: mask is int32 on device (bool -> int32), NOT bytes.
__global__ void crf_kernel(const int* __restrict__ mask,
                           const int* __restrict__ y,
                           const float* __restrict__ start,
                           const float* __restrict__ endv,
                           const float* __restrict__ trans) {
    const int b = blockIdx.x;
    const int lane = threadIdx.x;
    const float* emb = g_em + (size_t)b * TT * KTAG;
    const int* yb = y + b * TT;
    const int* mb = mask + b * TT;

    float tr[KTAG];
#pragma unroll
    for (int i = 0; i < KTAG; ++i)
        tr[i] = (lane < KTAG) ? trans[i * KTAG + lane] : 0.f;
    float alpha = (lane < KTAG) ? (start[lane] + emb[lane]) : -1e30f;

    // numerator pieces (lane-parallel over t)
    float num = 0.f; int msum = 0;
    for (int t = lane; t < TT; t += 32) {
        int mt = mb[t] ? 1 : 0;
        msum += mt;
        if (t >= 1 && mt) {
            int yt = yb[t], yp = yb[t - 1];
            num += emb[t * KTAG + yt] + trans[yp * KTAG + yt];
        }
    }
#pragma unroll
    for (int off = 16; off > 0; off >>= 1) {
        num  += __shfl_xor_sync(0xffffffffu, num, off);
        msum += __shfl_xor_sync(0xffffffffu, msum, off);
    }

    // forward recurrence (K=9 in lanes 0..8)
    for (int t = 1; t < TT; ++t) {
        float em_t = (lane < KTAG) ? emb[t * KTAG + lane] : 0.f;
        float v[KTAG], m = -1e30f;
#pragma unroll
        for (int i = 0; i < KTAG; ++i) {
            v[i] = __shfl_sync(0xffffffffu, alpha, i) + tr[i];
            m = fmaxf(m, v[i]);
        }
        float s = 0.f;
#pragma unroll
        for (int i = 0; i < KTAG; ++i) s += __expf(v[i] - m);
        float nxt = m + __logf(s) + em_t;
        alpha = mb[t] ? nxt : alpha;
    }

    // denominator = logsumexp(alpha + end)
    float av = (lane < KTAG) ? (alpha + endv[lane]) : -1e30f;
    float m = av;
#pragma unroll
    for (int off = 16; off > 0; off >>= 1)
        m = fmaxf(m, __shfl_xor_sync(0xffffffffu, m, off));
    float s = __expf(av - m);
#pragma unroll
    for (int off = 16; off > 0; off >>= 1)
        s += __shfl_xor_sync(0xffffffffu, s, off);
    float den = m + __logf(s);

    if (lane == 0) {
        int last = msum - 1;
        float numerator = num + start[yb[0]] + emb[yb[0]] + endv[yb[last]];
        g_nll[b] = den - numerator;
    }
}

// ---------------- final deterministic sum -------------------------------------
__global__ void final_kernel(float* __restrict__ out) {
    if (threadIdx.x == 0 && blockIdx.x == 0) {
        float s = 0.f;
        for (int b = 0; b < BB; ++b) s += g_nll[b];
        out[0] = s;
    }
}

// ---------------- launch -------------------------------------------------------
extern "C" void kernel_launch(void* const* d_in, const int* in_sizes, int n_in,
                              void* d_out, int out_size) {
    const float* emb   = (const float*)d_in[0];
    const int*   mask  = (const int*)d_in[1];     // bool stored as int32
    const int*   y     = (const int*)d_in[2];
    const float* w_ih0f = (const float*)d_in[3];
    const float* w_hh0f = (const float*)d_in[4];
    const float* b_ih0f = (const float*)d_in[5];
    const float* b_hh0f = (const float*)d_in[6];
    const float* w_ih0b = (const float*)d_in[7];
    const float* w_hh0b = (const float*)d_in[8];
    const float* b_ih0b = (const float*)d_in[9];
    const float* b_hh0b = (const float*)d_in[10];
    const float* w_ih1f = (const float*)d_in[11];
    const float* w_hh1f = (const float*)d_in[12];
    const float* b_ih1f = (const float*)d_in[13];
    const float* b_hh1f = (const float*)d_in[14];
    const float* w_ih1b = (const float*)d_in[15];
    const float* w_hh1b = (const float*)d_in[16];
    const float* b_ih1b = (const float*)d_in[17];
    const float* b_hh1b = (const float*)d_in[18];
    const float* w_out  = (const float*)d_in[19];
    const float* b_out  = (const float*)d_in[20];
    const float* crf_s  = (const float*)d_in[21];
    const float* crf_e  = (const float*)d_in[22];
    const float* crf_t  = (const float*)d_in[23];
    float* out = (float*)d_out;

    init_kernel<<<64, 256>>>();

    // ---- layer 0 ----
    pack_kernel<<<2048, 256>>>(w_ih0f, w_ih0b, b_ih0f, b_hh0f, b_ih0b, b_hh0b, EE);
    {
        dim3 grid(NG / 64, (BB * TT) / 128);
        gemm_tf32_kernel<<<grid, 256>>>(emb, EE, 0);
    }
    lstm_kernel<<<128, 256>>>(w_hh0f, w_hh0b, 0);

    // ---- layer 1 ----
    pack_kernel<<<2048, 256>>>(w_ih1f, w_ih1b, b_ih1f, b_hh1f, b_ih1b, b_hh1b, 2 * HH);
    {
        dim3 grid(NG / 64, (BB * TT) / 128);
        gemm_tf32_kernel<<<grid, 256>>>(nullptr, 2 * HH, 1);
    }
    lstm_kernel<<<128, 256>>>(w_hh1f, w_hh1b, 1);

    // ---- emissions + CRF ----
    emis_kernel<<<(BB * TT) / 8, 256>>>(w_out, b_out);
    crf_kernel<<<BB, 32>>>(mask, y, crf_s, crf_e, crf_t);
    final_kernel<<<1, 32>>>(out);
}